// round 6
// baseline (speedup 1.0000x reference)
#include <cuda_runtime.h>
#include <cuda_fp16.h>
#include <math.h>

// Problem constants
#define BB 8
#define NN 4096
#define CC 768
#define HH 8
#define DD 96
#define C3 2304
#define BH (BB*HH)
#define SPLITS 8
#define K3 1536   // 2*CC: fp16 split-K depth (A=[hi|lo], B=[hi;hi])

// Scratch (device globals — allocation-free kernel_launch)
__device__ float g_q[BB*HH*DD*NN];     // [b][h][d][n]
__device__ float g_k[BB*HH*DD*NN];
__device__ float g_v[BB*HH*DD*NN];
__device__ float g_rq[BB*HH*DD];
__device__ float g_rk[BB*HH*DD];
__device__ float g_part[SPLITS*BH*DD*DD];
__device__ float g_attn[BH*DD*DD];
__device__ float g_yt[BB*HH*DD*NN];    // y transposed: [b][h][d][n]

// fp16 split operands
__device__ __half g_xs[(size_t)BB*NN*K3];   // A' GEMM1: [32768][1536] = [hi|lo]
__device__ __half g_ws[(size_t)K3*C3];      // B' GEMM1: [1536][2304] = [hi;hi]
__device__ __half g_ys[(size_t)BB*NN*K3];   // A' GEMM2
__device__ __half g_wps[(size_t)K3*CC];     // B' GEMM2

// ---------------------------------------------------------------------------
// MMA / ldmatrix helpers
// ---------------------------------------------------------------------------
__device__ __forceinline__ void mma16816(float* c, const unsigned* a, const unsigned* b) {
    asm volatile(
        "mma.sync.aligned.m16n8k16.row.col.f32.f16.f16.f32 "
        "{%0,%1,%2,%3}, {%4,%5,%6,%7}, {%8,%9}, {%0,%1,%2,%3};"
        : "+f"(c[0]), "+f"(c[1]), "+f"(c[2]), "+f"(c[3])
        : "r"(a[0]), "r"(a[1]), "r"(a[2]), "r"(a[3]), "r"(b[0]), "r"(b[1]));
}
__device__ __forceinline__ void ldsm_x4(unsigned* r, const void* p) {
    unsigned addr = (unsigned)__cvta_generic_to_shared(p);
    asm volatile("ldmatrix.sync.aligned.m8n8.x4.shared.b16 {%0,%1,%2,%3}, [%4];"
        : "=r"(r[0]), "=r"(r[1]), "=r"(r[2]), "=r"(r[3]) : "r"(addr));
}
__device__ __forceinline__ void ldsm_x4_t(unsigned* r, const void* p) {
    unsigned addr = (unsigned)__cvta_generic_to_shared(p);
    asm volatile("ldmatrix.sync.aligned.m8n8.x4.trans.shared.b16 {%0,%1,%2,%3}, [%4];"
        : "=r"(r[0]), "=r"(r[1]), "=r"(r[2]), "=r"(r[3]) : "r"(addr));
}
__device__ __forceinline__ void split_hl(float v, __half& hi, __half& lo) {
    hi = __float2half(v);
    lo = __float2half(v - __half2float(hi));
}

// ---------------------------------------------------------------------------
// Split kernels: fp32 -> fp16 blocks along K
// ---------------------------------------------------------------------------
__global__ __launch_bounds__(256) void split_x_kernel(const float* __restrict__ x)
{
    int idx = blockIdx.x * 256 + threadIdx.x;
    int m = idx / (CC / 4);
    int k4 = (idx - m * (CC / 4)) * 4;
    float4 v = *(const float4*)&x[(size_t)m * CC + k4];
    __half hi[4], lo[4];
    split_hl(v.x, hi[0], lo[0]); split_hl(v.y, hi[1], lo[1]);
    split_hl(v.z, hi[2], lo[2]); split_hl(v.w, hi[3], lo[3]);
    __half* base = g_xs + (size_t)m * K3 + k4;
    *(uint2*)(base)      = *(uint2*)hi;
    *(uint2*)(base + CC) = *(uint2*)lo;
}

__global__ __launch_bounds__(256) void split_wqkv_kernel(const float* __restrict__ w)
{
    int idx = blockIdx.x * 256 + threadIdx.x;
    int k = idx / (C3 / 4);
    int n4 = (idx - k * (C3 / 4)) * 4;
    float4 v = *(const float4*)&w[(size_t)k * C3 + n4];
    __half hi[4];
    hi[0] = __float2half(v.x); hi[1] = __float2half(v.y);
    hi[2] = __float2half(v.z); hi[3] = __float2half(v.w);
    *(uint2*)&g_ws[(size_t)k * C3 + n4]        = *(uint2*)hi;
    *(uint2*)&g_ws[(size_t)(k + CC) * C3 + n4] = *(uint2*)hi;
}

__global__ __launch_bounds__(256) void split_wproj_kernel(const float* __restrict__ w)
{
    int idx = blockIdx.x * 256 + threadIdx.x;
    int k = idx / (CC / 4);
    int n4 = (idx - k * (CC / 4)) * 4;
    float4 v = *(const float4*)&w[(size_t)k * CC + n4];
    __half hi[4];
    hi[0] = __float2half(v.x); hi[1] = __float2half(v.y);
    hi[2] = __float2half(v.z); hi[3] = __float2half(v.w);
    *(uint2*)&g_wps[(size_t)k * CC + n4]        = *(uint2*)hi;
    *(uint2*)&g_wps[(size_t)(k + CC) * CC + n4] = *(uint2*)hi;
}

// Transpose g_yt [b][c][n] f32 -> g_ys [b*N+n][hi|lo over c] fp16
__global__ __launch_bounds__(256) void ysplit_kernel()
{
    __shared__ float sm[32][33];
    const int n0 = blockIdx.x * 32;
    const int c0 = blockIdx.y * 32;
    const int b  = blockIdx.z;
    const int tx = threadIdx.x, ty = threadIdx.y;   // 32 x 8
#pragma unroll
    for (int i = 0; i < 4; i++) {
        int c = c0 + ty + i * 8;
        sm[ty + i * 8][tx] = g_yt[((size_t)b * CC + c) * NN + n0 + tx];
    }
    __syncthreads();
#pragma unroll
    for (int i = 0; i < 4; i++) {
        int n = n0 + ty + i * 8;
        int c = c0 + tx;
        __half hi, lo;
        split_hl(sm[tx][ty + i * 8], hi, lo);
        __half* base = g_ys + ((size_t)b * NN + n) * K3;
        base[c]      = hi;
        base[CC + c] = lo;
    }
}

// ---------------------------------------------------------------------------
// fp16 MMA GEMM: C[M x Ncols] = A'[M x 1536] * B'[1536 x Ncols]  (fp32 accum)
// BM=128, BN=256, BK=32, 256 threads = 8 warps (2m x 4n), warp tile 64x64.
// Register-prefetch of chunk t+1 overlapped with compute of chunk t.
// mode 0: scatter GEMM1 output into g_q/g_k/g_v.  mode 1: out = C + bias.
// ---------------------------------------------------------------------------
__global__ __launch_bounds__(256) void mma_gemm_kernel(
    int Ncols, int mode, const float* __restrict__ bias, float* __restrict__ out)
{
    __shared__ __align__(16) __half As[128][40];   // stride 40: ldsm conflict-free (5r+g)
    __shared__ __align__(16) __half Bs[32][264];   // stride 264: ldsm conflict-free (33r+g)
    const __half* __restrict__ A  = mode ? g_ys  : g_xs;
    const __half* __restrict__ Bm = mode ? g_wps : g_ws;

    const int tid = threadIdx.x;
    const int wid = tid >> 5, lane = tid & 31;
    const int rowBase = blockIdx.y * 128;
    const int colBase = blockIdx.x * 256;
    const int warpM = (wid & 1) * 64;
    const int warpN = (wid >> 1) * 64;

    float acc[4][8][4];
#pragma unroll
    for (int i = 0; i < 4; i++)
#pragma unroll
        for (int j = 0; j < 8; j++)
#pragma unroll
            for (int q = 0; q < 4; q++) acc[i][j][q] = 0.f;

    // global load mapping
    const int arow = tid >> 2, acol = (tid & 3) * 8;     // A: 2 passes (+64 rows)
    const int brow = tid >> 5, bcol = (tid & 31) * 8;    // B: 4 passes (+8 rows)

    const __half* aptr = A  + (size_t)(rowBase + arow) * K3 + acol;
    const __half* bptr = Bm + (size_t)brow * Ncols + colBase + bcol;

    uint4 ar[2], br[4];
#pragma unroll
    for (int p = 0; p < 2; p++) ar[p] = *(const uint4*)(aptr + (size_t)p * 64 * K3);
#pragma unroll
    for (int p = 0; p < 4; p++) br[p] = *(const uint4*)(bptr + (size_t)p * 8 * Ncols);

#pragma unroll
    for (int p = 0; p < 2; p++) *(uint4*)&As[arow + p * 64][acol] = ar[p];
#pragma unroll
    for (int p = 0; p < 4; p++) *(uint4*)&Bs[brow + p * 8][bcol] = br[p];
    __syncthreads();

    const int NT = K3 / 32;
    for (int t = 0; t < NT; t++) {
        // prefetch chunk t+1 into registers (LDG latency hidden by compute below)
        if (t + 1 < NT) {
            const int k0 = (t + 1) * 32;
#pragma unroll
            for (int p = 0; p < 2; p++)
                ar[p] = *(const uint4*)(aptr + (size_t)p * 64 * K3 + k0);
#pragma unroll
            for (int p = 0; p < 4; p++)
                br[p] = *(const uint4*)(bptr + ((size_t)k0 + p * 8) * Ncols);
        }

        // compute chunk t from SMEM
#pragma unroll
        for (int ks = 0; ks < 2; ks++) {
            unsigned af[4][4];
#pragma unroll
            for (int im = 0; im < 4; im++)
                ldsm_x4(af[im], &As[warpM + im * 16 + (lane & 15)]
                                   [ks * 16 + (lane >> 4) * 8]);
            unsigned bf[8][2];
#pragma unroll
            for (int g = 0; g < 4; g++) {
                unsigned r[4];
                ldsm_x4_t(r, &Bs[ks * 16 + ((lane >> 3) & 1) * 8 + (lane & 7)]
                             [warpN + g * 16 + (lane >> 4) * 8]);
                bf[2 * g][0] = r[0]; bf[2 * g][1] = r[1];
                bf[2 * g + 1][0] = r[2]; bf[2 * g + 1][1] = r[3];
            }
#pragma unroll
            for (int im = 0; im < 4; im++)
#pragma unroll
                for (int jn = 0; jn < 8; jn++)
                    mma16816(acc[im][jn], af[im], bf[jn]);
        }

        if (t + 1 < NT) {
            __syncthreads();   // all warps done reading chunk t
#pragma unroll
            for (int p = 0; p < 2; p++) *(uint4*)&As[arow + p * 64][acol] = ar[p];
#pragma unroll
            for (int p = 0; p < 4; p++) *(uint4*)&Bs[brow + p * 8][bcol] = br[p];
            __syncthreads();
        }
    }

    // Epilogue
#pragma unroll
    for (int im = 0; im < 4; im++) {
#pragma unroll
        for (int jn = 0; jn < 8; jn++) {
#pragma unroll
            for (int q = 0; q < 4; q++) {
                int m = warpM + im * 16 + (lane >> 2) + (q >> 1) * 8;
                int n = warpN + jn * 8 + (lane & 3) * 2 + (q & 1);
                float val = acc[im][jn][q];
                int row = rowBase + m;
                int col = colBase + n;
                if (mode == 0) {
                    int b = row >> 12;
                    int nn2 = row & 4095;
                    int h = col / 288;
                    int rem = col - h * 288;
                    int d = rem / 3;
                    int s = rem - d * 3;
                    float* dst = (s == 0) ? g_q : (s == 1) ? g_k : g_v;
                    dst[((b * HH + h) * DD + d) * NN + nn2] = val;
                } else {
                    out[(size_t)row * CC + col] = val + bias[col];
                }
            }
        }
    }
}

// ---------------------------------------------------------------------------
// Kernel: per-(b,h,d) inverse L2 norm over N for q (y=0) and k (y=1)
// ---------------------------------------------------------------------------
__global__ __launch_bounds__(256) void norm_kernel()
{
    const int row = blockIdx.x;
    const float* src = (blockIdx.y == 0) ? g_q : g_k;
    float*       dst = (blockIdx.y == 0) ? g_rq : g_rk;
    const float* p = src + (size_t)row * NN;
    float s = 0.f;
    for (int i = threadIdx.x; i < NN; i += 256) {
        float v = p[i];
        s = fmaf(v, v, s);
    }
#pragma unroll
    for (int off = 16; off; off >>= 1) s += __shfl_down_sync(0xffffffffu, s, off);
    __shared__ float ws[8];
    if ((threadIdx.x & 31) == 0) ws[threadIdx.x >> 5] = s;
    __syncthreads();
    if (threadIdx.x < 8) {
        float t = ws[threadIdx.x];
#pragma unroll
        for (int off = 4; off; off >>= 1) t += __shfl_down_sync(0xffu, t, off);
        if (threadIdx.x == 0) dst[row] = rsqrtf(t);
    }
}

// ---------------------------------------------------------------------------
// Kernel: cross-covariance partials (FFMA; small)
// ---------------------------------------------------------------------------
__global__ __launch_bounds__(256) void attn_part_kernel()
{
    __shared__ float Qs[32][97];
    __shared__ float Ks[32][97];
    const int tid = threadIdx.x;
    const int bh = blockIdx.x;
    const int n0 = blockIdx.y * (NN / SPLITS);
    const float* qp = g_q + (size_t)bh * DD * NN;
    const float* kp = g_k + (size_t)bh * DD * NN;
    const int tx = tid & 15;
    const int ty = tid >> 4;

    float acc[6][6];
#pragma unroll
    for (int i = 0; i < 6; i++)
#pragma unroll
        for (int j = 0; j < 6; j++) acc[i][j] = 0.f;

    for (int nc = 0; nc < NN / SPLITS; nc += 32) {
#pragma unroll
        for (int p = 0; p < 12; p++) {
            int idx = p * 256 + tid;
            int nn2 = idx & 31, d = idx >> 5;
            Qs[nn2][d] = qp[d * NN + n0 + nc + nn2];
            Ks[nn2][d] = kp[d * NN + n0 + nc + nn2];
        }
        __syncthreads();
#pragma unroll
        for (int kk = 0; kk < 32; kk++) {
            float fq[6], fk[6];
#pragma unroll
            for (int i = 0; i < 6; i++) fq[i] = Qs[kk][ty * 6 + i];
#pragma unroll
            for (int j = 0; j < 6; j++) fk[j] = Ks[kk][tx * 6 + j];
#pragma unroll
            for (int i = 0; i < 6; i++)
#pragma unroll
                for (int j = 0; j < 6; j++)
                    acc[i][j] = fmaf(fq[i], fk[j], acc[i][j]);
        }
        __syncthreads();
    }

    float* dst = g_part + ((size_t)blockIdx.y * BH + bh) * DD * DD;
#pragma unroll
    for (int i = 0; i < 6; i++)
#pragma unroll
        for (int j = 0; j < 6; j++)
            dst[(ty * 6 + i) * DD + tx * 6 + j] = acc[i][j];
}

// ---------------------------------------------------------------------------
// Kernel: reduce split-K partials, apply norms * temp, softmax over e.
// ---------------------------------------------------------------------------
__global__ __launch_bounds__(128) void softmax_kernel(const float* __restrict__ temp)
{
    const int bhd = blockIdx.x;
    const int bh = bhd / DD;
    const int d  = bhd - bh * DD;
    const int h  = bh & (HH - 1);
    const int e  = threadIdx.x;

    float raw = 0.f;
    float val = -1e30f;
    if (e < DD) {
        float s = 0.f;
#pragma unroll
        for (int sp = 0; sp < SPLITS; sp++)
            s += g_part[(((size_t)sp * BH + bh) * DD + d) * DD + e];
        raw = s * g_rq[bh * DD + d] * g_rk[bh * DD + e] * temp[h];
        val = raw;
    }

    __shared__ float red[128];
    red[e] = val;
    __syncthreads();
#pragma unroll
    for (int off = 64; off >= 1; off >>= 1) {
        if (e < off) red[e] = fmaxf(red[e], red[e + off]);
        __syncthreads();
    }
    float m = red[0];
    __syncthreads();

    float ex = (e < DD) ? expf(raw - m) : 0.f;
    red[e] = ex;
    __syncthreads();
#pragma unroll
    for (int off = 64; off >= 1; off >>= 1) {
        if (e < off) red[e] += red[e + off];
        __syncthreads();
    }
    float sum = red[0];

    if (e < DD)
        g_attn[((size_t)bh * DD + d) * DD + e] = ex / sum;
}

// ---------------------------------------------------------------------------
// Kernel: y_t[d][n] = sum_e attn[d][e] * v[e][n] (FFMA; small)
// ---------------------------------------------------------------------------
__global__ __launch_bounds__(256) void av_kernel()
{
    __shared__ float As_[96][33];
    __shared__ float Vs[32][128];
    const int tid = threadIdx.x;
    const int bh = blockIdx.x;
    const int n0 = blockIdx.y * 128;
    const float* ap = g_attn + (size_t)bh * DD * DD;
    const float* vp = g_v + (size_t)bh * DD * NN;
    const int tx = tid & 15;
    const int ty = tid >> 4;

    float acc[6][8];
#pragma unroll
    for (int i = 0; i < 6; i++)
#pragma unroll
        for (int j = 0; j < 8; j++) acc[i][j] = 0.f;

    for (int ec = 0; ec < DD; ec += 32) {
#pragma unroll
        for (int p = 0; p < 12; p++) {
            int idx = p * 256 + tid;
            int ee = idx & 31, d = idx >> 5;
            As_[d][ee] = ap[d * DD + ec + ee];
        }
#pragma unroll
        for (int p = 0; p < 16; p++) {
            int idx = p * 256 + tid;
            int nn2 = idx & 127, ee = idx >> 7;
            Vs[ee][nn2] = vp[(size_t)(ec + ee) * NN + n0 + nn2];
        }
        __syncthreads();
#pragma unroll
        for (int kk = 0; kk < 32; kk++) {
            float fa[6];
#pragma unroll
            for (int i = 0; i < 6; i++) fa[i] = As_[ty * 6 + i][kk];
            float4 v0 = *(const float4*)&Vs[kk][tx * 8];
            float4 v1 = *(const float4*)&Vs[kk][tx * 8 + 4];
            float fv[8] = {v0.x, v0.y, v0.z, v0.w, v1.x, v1.y, v1.z, v1.w};
#pragma unroll
            for (int i = 0; i < 6; i++)
#pragma unroll
                for (int j = 0; j < 8; j++)
                    acc[i][j] = fmaf(fa[i], fv[j], acc[i][j]);
        }
        __syncthreads();
    }

    float* yp = g_yt + (size_t)bh * DD * NN;
#pragma unroll
    for (int i = 0; i < 6; i++) {
        int d = ty * 6 + i;
        float4 o0 = {acc[i][0], acc[i][1], acc[i][2], acc[i][3]};
        float4 o1 = {acc[i][4], acc[i][5], acc[i][6], acc[i][7]};
        *(float4*)&yp[(size_t)d * NN + n0 + tx * 8]     = o0;
        *(float4*)&yp[(size_t)d * NN + n0 + tx * 8 + 4] = o1;
    }
}

// ---------------------------------------------------------------------------
extern "C" void kernel_launch(void* const* d_in, const int* in_sizes, int n_in,
                              void* d_out, int out_size)
{
    const float* x      = (const float*)d_in[0];
    const float* w_qkv  = (const float*)d_in[1];
    const float* w_proj = (const float*)d_in[2];
    const float* b_proj = (const float*)d_in[3];
    const float* temp   = (const float*)d_in[4];
    float* out = (float*)d_out;

    split_x_kernel<<<(BB * NN * CC / 4) / 256, 256>>>(x);
    split_wqkv_kernel<<<(CC * C3 / 4) / 256, 256>>>(w_qkv);
    split_wproj_kernel<<<(CC * CC / 4) / 256, 256>>>(w_proj);

    // GEMM1: [32768 x 1536] x [1536 x 2304] -> scatter q/k/v
    mma_gemm_kernel<<<dim3(C3 / 256, (BB * NN) / 128), 256>>>(C3, 0, nullptr, nullptr);

    norm_kernel<<<dim3(BH * DD, 2), 256>>>();
    attn_part_kernel<<<dim3(BH, SPLITS), 256>>>();
    softmax_kernel<<<BH * DD, 128>>>(temp);
    av_kernel<<<dim3(BH, NN / 128), 256>>>();

    ysplit_kernel<<<dim3(NN / 32, CC / 32, BB), dim3(32, 8)>>>();

    // GEMM2: [32768 x 1536] x [1536 x 768] -> out + bias
    mma_gemm_kernel<<<dim3(CC / 256, (BB * NN) / 128), 256>>>(CC, 1, b_proj, out);
}

// round 7
// speedup vs baseline: 1.2616x; 1.2616x over previous
#include <cuda_runtime.h>
#include <cuda_fp16.h>
#include <math.h>

// Problem constants
#define BB 8
#define NN 4096
#define CC 768
#define HH 8
#define DD 96
#define C3 2304
#define BH (BB*HH)
#define SPLITS 8
#define K3 1536   // 2*CC: fp16 split-K depth (A=[hi|lo], B=[hi;hi])

// Scratch (device globals — allocation-free kernel_launch)
__device__ float g_q[BB*HH*DD*NN];     // [b][h][d][n]
__device__ float g_k[BB*HH*DD*NN];
__device__ float g_v[BB*HH*DD*NN];
__device__ float g_rq[BB*HH*DD];
__device__ float g_rk[BB*HH*DD];
__device__ float g_part[SPLITS*BH*DD*DD];
__device__ float g_attn[BH*DD*DD];
__device__ float g_yt[BB*HH*DD*NN];    // y transposed: [b][h][d][n]

// fp16 split operands
__device__ __half g_xs[(size_t)BB*NN*K3];   // A' GEMM1: [32768][1536] = [hi|lo]
__device__ __half g_ws[(size_t)K3*C3];      // B' GEMM1: [1536][2304] = [hi;hi]
__device__ __half g_ys[(size_t)BB*NN*K3];   // A' GEMM2
__device__ __half g_wps[(size_t)K3*CC];     // B' GEMM2

// ---------------------------------------------------------------------------
// MMA / ldmatrix / cp.async helpers
// ---------------------------------------------------------------------------
__device__ __forceinline__ void mma16816(float* c, const unsigned* a, const unsigned* b) {
    asm volatile(
        "mma.sync.aligned.m16n8k16.row.col.f32.f16.f16.f32 "
        "{%0,%1,%2,%3}, {%4,%5,%6,%7}, {%8,%9}, {%0,%1,%2,%3};"
        : "+f"(c[0]), "+f"(c[1]), "+f"(c[2]), "+f"(c[3])
        : "r"(a[0]), "r"(a[1]), "r"(a[2]), "r"(a[3]), "r"(b[0]), "r"(b[1]));
}
__device__ __forceinline__ void ldsm_x4(unsigned* r, const void* p) {
    unsigned addr = (unsigned)__cvta_generic_to_shared(p);
    asm volatile("ldmatrix.sync.aligned.m8n8.x4.shared.b16 {%0,%1,%2,%3}, [%4];"
        : "=r"(r[0]), "=r"(r[1]), "=r"(r[2]), "=r"(r[3]) : "r"(addr));
}
__device__ __forceinline__ void ldsm_x4_t(unsigned* r, const void* p) {
    unsigned addr = (unsigned)__cvta_generic_to_shared(p);
    asm volatile("ldmatrix.sync.aligned.m8n8.x4.trans.shared.b16 {%0,%1,%2,%3}, [%4];"
        : "=r"(r[0]), "=r"(r[1]), "=r"(r[2]), "=r"(r[3]) : "r"(addr));
}
__device__ __forceinline__ void cp16(const void* smem_dst, const void* gsrc) {
    unsigned d = (unsigned)__cvta_generic_to_shared(smem_dst);
    asm volatile("cp.async.cg.shared.global [%0], [%1], 16;" :: "r"(d), "l"(gsrc));
}
#define CP_COMMIT() asm volatile("cp.async.commit_group;" ::: "memory")
#define CP_WAIT0()  asm volatile("cp.async.wait_group 0;" ::: "memory")

__device__ __forceinline__ void split_hl(float v, __half& hi, __half& lo) {
    hi = __float2half(v);
    lo = __float2half(v - __half2float(hi));
}

// ---------------------------------------------------------------------------
// Split kernels: fp32 -> fp16 blocks along K
// ---------------------------------------------------------------------------
__global__ __launch_bounds__(256) void split_x_kernel(const float* __restrict__ x)
{
    int idx = blockIdx.x * 256 + threadIdx.x;
    int m = idx / (CC / 4);
    int k4 = (idx - m * (CC / 4)) * 4;
    float4 v = *(const float4*)&x[(size_t)m * CC + k4];
    __half hi[4], lo[4];
    split_hl(v.x, hi[0], lo[0]); split_hl(v.y, hi[1], lo[1]);
    split_hl(v.z, hi[2], lo[2]); split_hl(v.w, hi[3], lo[3]);
    __half* base = g_xs + (size_t)m * K3 + k4;
    *(uint2*)(base)      = *(uint2*)hi;
    *(uint2*)(base + CC) = *(uint2*)lo;
}

__global__ __launch_bounds__(256) void split_wqkv_kernel(const float* __restrict__ w)
{
    int idx = blockIdx.x * 256 + threadIdx.x;
    int k = idx / (C3 / 4);
    int n4 = (idx - k * (C3 / 4)) * 4;
    float4 v = *(const float4*)&w[(size_t)k * C3 + n4];
    __half hi[4];
    hi[0] = __float2half(v.x); hi[1] = __float2half(v.y);
    hi[2] = __float2half(v.z); hi[3] = __float2half(v.w);
    *(uint2*)&g_ws[(size_t)k * C3 + n4]        = *(uint2*)hi;
    *(uint2*)&g_ws[(size_t)(k + CC) * C3 + n4] = *(uint2*)hi;
}

__global__ __launch_bounds__(256) void split_wproj_kernel(const float* __restrict__ w)
{
    int idx = blockIdx.x * 256 + threadIdx.x;
    int k = idx / (CC / 4);
    int n4 = (idx - k * (CC / 4)) * 4;
    float4 v = *(const float4*)&w[(size_t)k * CC + n4];
    __half hi[4];
    hi[0] = __float2half(v.x); hi[1] = __float2half(v.y);
    hi[2] = __float2half(v.z); hi[3] = __float2half(v.w);
    *(uint2*)&g_wps[(size_t)k * CC + n4]        = *(uint2*)hi;
    *(uint2*)&g_wps[(size_t)(k + CC) * CC + n4] = *(uint2*)hi;
}

// Transpose g_yt [b][c][n] f32 -> g_ys [b*N+n][hi|lo over c] fp16
__global__ __launch_bounds__(256) void ysplit_kernel()
{
    __shared__ float sm[32][33];
    const int n0 = blockIdx.x * 32;
    const int c0 = blockIdx.y * 32;
    const int b  = blockIdx.z;
    const int tx = threadIdx.x, ty = threadIdx.y;   // 32 x 8
#pragma unroll
    for (int i = 0; i < 4; i++) {
        int c = c0 + ty + i * 8;
        sm[ty + i * 8][tx] = g_yt[((size_t)b * CC + c) * NN + n0 + tx];
    }
    __syncthreads();
#pragma unroll
    for (int i = 0; i < 4; i++) {
        int n = n0 + ty + i * 8;
        int c = c0 + tx;
        __half hi, lo;
        split_hl(sm[tx][ty + i * 8], hi, lo);
        __half* base = g_ys + ((size_t)b * NN + n) * K3;
        base[c]      = hi;
        base[CC + c] = lo;
    }
}

// ---------------------------------------------------------------------------
// fp16 MMA GEMM: C[M x Ncols] = A'[M x 1536] * B'[1536 x Ncols]  (fp32 accum)
// BM=128, BN=128, BK=32. 128 threads = 4 warps (2m x 2n), warp tile 64x64.
// cp.async double-buffered SMEM; 2 CTAs/SM for cross-CTA latency hiding.
// mode 0: scatter GEMM1 output into g_q/g_k/g_v.  mode 1: out = C + bias.
// ---------------------------------------------------------------------------
__global__ __launch_bounds__(128, 2) void mma_gemm_kernel(
    int Ncols, int mode, const float* __restrict__ bias, float* __restrict__ out)
{
    __shared__ __align__(16) __half As[2][128][40];   // stride 40: ldsm conflict-free
    __shared__ __align__(16) __half Bs[2][32][136];   // stride 136: ldsm conflict-free
    const __half* __restrict__ A  = mode ? g_ys  : g_xs;
    const __half* __restrict__ Bm = mode ? g_wps : g_ws;

    const int tid = threadIdx.x;
    const int wid = tid >> 5, lane = tid & 31;
    const int rowBase = blockIdx.y * 128;
    const int colBase = blockIdx.x * 128;
    const int warpM = (wid & 1) * 64;
    const int warpN = (wid >> 1) * 64;

    float acc[4][8][4];
#pragma unroll
    for (int i = 0; i < 4; i++)
#pragma unroll
        for (int j = 0; j < 8; j++)
#pragma unroll
            for (int q = 0; q < 4; q++) acc[i][j][q] = 0.f;

    // cp.async mapping: A chunk = 128 rows x 32 halves (4 x 16B segs/row)
    //                   B chunk = 32 rows x 128 halves (16 segs/row)
    const int ar = tid >> 2, ac = (tid & 3) * 8;      // 4 passes: +32 rows
    const int br = tid >> 4, bc2 = (tid & 15) * 8;    // 4 passes: +8 rows

    const __half* aptr = A  + (size_t)(rowBase + ar) * K3 + ac;
    const __half* bptr = Bm + (size_t)br * Ncols + colBase + bc2;

    // prologue: prefetch chunk 0 -> buf 0
#pragma unroll
    for (int p = 0; p < 4; p++)
        cp16(&As[0][ar + p * 32][ac], aptr + (size_t)p * 32 * K3);
#pragma unroll
    for (int p = 0; p < 4; p++)
        cp16(&Bs[0][br + p * 8][bc2], bptr + (size_t)p * 8 * Ncols);
    CP_COMMIT();

    const int NT = K3 / 32;
    for (int t = 0; t < NT; t++) {
        const int buf = t & 1;
        CP_WAIT0();
        __syncthreads();   // buf[t] ready; all warps done with buf[t^1]'s previous use

        if (t + 1 < NT) {
            const int k0 = (t + 1) * 32;
            const int nb = buf ^ 1;
#pragma unroll
            for (int p = 0; p < 4; p++)
                cp16(&As[nb][ar + p * 32][ac], aptr + (size_t)p * 32 * K3 + k0);
#pragma unroll
            for (int p = 0; p < 4; p++)
                cp16(&Bs[nb][br + p * 8][bc2], bptr + ((size_t)k0 + p * 8) * Ncols);
            CP_COMMIT();
        }

        // compute chunk t from buf
#pragma unroll
        for (int ks = 0; ks < 2; ks++) {
            unsigned af[4][4];
#pragma unroll
            for (int im = 0; im < 4; im++)
                ldsm_x4(af[im], &As[buf][warpM + im * 16 + (lane & 15)]
                                   [ks * 16 + (lane >> 4) * 8]);
            unsigned bf[8][2];
#pragma unroll
            for (int g = 0; g < 4; g++) {
                unsigned r[4];
                ldsm_x4_t(r, &Bs[buf][ks * 16 + ((lane >> 3) & 1) * 8 + (lane & 7)]
                             [warpN + g * 16 + (lane >> 4) * 8]);
                bf[2 * g][0] = r[0]; bf[2 * g][1] = r[1];
                bf[2 * g + 1][0] = r[2]; bf[2 * g + 1][1] = r[3];
            }
#pragma unroll
            for (int im = 0; im < 4; im++)
#pragma unroll
                for (int jn = 0; jn < 8; jn++)
                    mma16816(acc[im][jn], af[im], bf[jn]);
        }
    }

    // Epilogue
#pragma unroll
    for (int im = 0; im < 4; im++) {
#pragma unroll
        for (int jn = 0; jn < 8; jn++) {
#pragma unroll
            for (int q = 0; q < 4; q++) {
                int m = warpM + im * 16 + (lane >> 2) + (q >> 1) * 8;
                int n = warpN + jn * 8 + (lane & 3) * 2 + (q & 1);
                float val = acc[im][jn][q];
                int row = rowBase + m;
                int col = colBase + n;
                if (mode == 0) {
                    int b = row >> 12;
                    int nn2 = row & 4095;
                    int h = col / 288;
                    int rem = col - h * 288;
                    int d = rem / 3;
                    int s = rem - d * 3;
                    float* dst = (s == 0) ? g_q : (s == 1) ? g_k : g_v;
                    dst[((b * HH + h) * DD + d) * NN + nn2] = val;
                } else {
                    out[(size_t)row * CC + col] = val + bias[col];
                }
            }
        }
    }
}

// ---------------------------------------------------------------------------
// Kernel: per-(b,h,d) inverse L2 norm over N for q (y=0) and k (y=1)
// ---------------------------------------------------------------------------
__global__ __launch_bounds__(256) void norm_kernel()
{
    const int row = blockIdx.x;
    const float* src = (blockIdx.y == 0) ? g_q : g_k;
    float*       dst = (blockIdx.y == 0) ? g_rq : g_rk;
    const float* p = src + (size_t)row * NN;
    float s = 0.f;
    for (int i = threadIdx.x; i < NN; i += 256) {
        float v = p[i];
        s = fmaf(v, v, s);
    }
#pragma unroll
    for (int off = 16; off; off >>= 1) s += __shfl_down_sync(0xffffffffu, s, off);
    __shared__ float ws[8];
    if ((threadIdx.x & 31) == 0) ws[threadIdx.x >> 5] = s;
    __syncthreads();
    if (threadIdx.x < 8) {
        float t = ws[threadIdx.x];
#pragma unroll
        for (int off = 4; off; off >>= 1) t += __shfl_down_sync(0xffu, t, off);
        if (threadIdx.x == 0) dst[row] = rsqrtf(t);
    }
}

// ---------------------------------------------------------------------------
// Kernel: cross-covariance partials (FFMA; small)
// ---------------------------------------------------------------------------
__global__ __launch_bounds__(256) void attn_part_kernel()
{
    __shared__ float Qs[32][97];
    __shared__ float Ks[32][97];
    const int tid = threadIdx.x;
    const int bh = blockIdx.x;
    const int n0 = blockIdx.y * (NN / SPLITS);
    const float* qp = g_q + (size_t)bh * DD * NN;
    const float* kp = g_k + (size_t)bh * DD * NN;
    const int tx = tid & 15;
    const int ty = tid >> 4;

    float acc[6][6];
#pragma unroll
    for (int i = 0; i < 6; i++)
#pragma unroll
        for (int j = 0; j < 6; j++) acc[i][j] = 0.f;

    for (int nc = 0; nc < NN / SPLITS; nc += 32) {
#pragma unroll
        for (int p = 0; p < 12; p++) {
            int idx = p * 256 + tid;
            int nn2 = idx & 31, d = idx >> 5;
            Qs[nn2][d] = qp[d * NN + n0 + nc + nn2];
            Ks[nn2][d] = kp[d * NN + n0 + nc + nn2];
        }
        __syncthreads();
#pragma unroll
        for (int kk = 0; kk < 32; kk++) {
            float fq[6], fk[6];
#pragma unroll
            for (int i = 0; i < 6; i++) fq[i] = Qs[kk][ty * 6 + i];
#pragma unroll
            for (int j = 0; j < 6; j++) fk[j] = Ks[kk][tx * 6 + j];
#pragma unroll
            for (int i = 0; i < 6; i++)
#pragma unroll
                for (int j = 0; j < 6; j++)
                    acc[i][j] = fmaf(fq[i], fk[j], acc[i][j]);
        }
        __syncthreads();
    }

    float* dst = g_part + ((size_t)blockIdx.y * BH + bh) * DD * DD;
#pragma unroll
    for (int i = 0; i < 6; i++)
#pragma unroll
        for (int j = 0; j < 6; j++)
            dst[(ty * 6 + i) * DD + tx * 6 + j] = acc[i][j];
}

// ---------------------------------------------------------------------------
// Kernel: reduce split-K partials, apply norms * temp, softmax over e.
// ---------------------------------------------------------------------------
__global__ __launch_bounds__(128) void softmax_kernel(const float* __restrict__ temp)
{
    const int bhd = blockIdx.x;
    const int bh = bhd / DD;
    const int d  = bhd - bh * DD;
    const int h  = bh & (HH - 1);
    const int e  = threadIdx.x;

    float raw = 0.f;
    float val = -1e30f;
    if (e < DD) {
        float s = 0.f;
#pragma unroll
        for (int sp = 0; sp < SPLITS; sp++)
            s += g_part[(((size_t)sp * BH + bh) * DD + d) * DD + e];
        raw = s * g_rq[bh * DD + d] * g_rk[bh * DD + e] * temp[h];
        val = raw;
    }

    __shared__ float red[128];
    red[e] = val;
    __syncthreads();
#pragma unroll
    for (int off = 64; off >= 1; off >>= 1) {
        if (e < off) red[e] = fmaxf(red[e], red[e + off]);
        __syncthreads();
    }
    float m = red[0];
    __syncthreads();

    float ex = (e < DD) ? expf(raw - m) : 0.f;
    red[e] = ex;
    __syncthreads();
#pragma unroll
    for (int off = 64; off >= 1; off >>= 1) {
        if (e < off) red[e] += red[e + off];
        __syncthreads();
    }
    float sum = red[0];

    if (e < DD)
        g_attn[((size_t)bh * DD + d) * DD + e] = ex / sum;
}

// ---------------------------------------------------------------------------
// Kernel: y_t[d][n] = sum_e attn[d][e] * v[e][n] (FFMA; small)
// ---------------------------------------------------------------------------
__global__ __launch_bounds__(256) void av_kernel()
{
    __shared__ float As_[96][33];
    __shared__ float Vs[32][128];
    const int tid = threadIdx.x;
    const int bh = blockIdx.x;
    const int n0 = blockIdx.y * 128;
    const float* ap = g_attn + (size_t)bh * DD * DD;
    const float* vp = g_v + (size_t)bh * DD * NN;
    const int tx = tid & 15;
    const int ty = tid >> 4;

    float acc[6][8];
#pragma unroll
    for (int i = 0; i < 6; i++)
#pragma unroll
        for (int j = 0; j < 8; j++) acc[i][j] = 0.f;

    for (int ec = 0; ec < DD; ec += 32) {
#pragma unroll
        for (int p = 0; p < 12; p++) {
            int idx = p * 256 + tid;
            int ee = idx & 31, d = idx >> 5;
            As_[d][ee] = ap[d * DD + ec + ee];
        }
#pragma unroll
        for (int p = 0; p < 16; p++) {
            int idx = p * 256 + tid;
            int nn2 = idx & 127, ee = idx >> 7;
            Vs[ee][nn2] = vp[(size_t)(ec + ee) * NN + n0 + nn2];
        }
        __syncthreads();
#pragma unroll
        for (int kk = 0; kk < 32; kk++) {
            float fa[6];
#pragma unroll
            for (int i = 0; i < 6; i++) fa[i] = As_[ty * 6 + i][kk];
            float4 v0 = *(const float4*)&Vs[kk][tx * 8];
            float4 v1 = *(const float4*)&Vs[kk][tx * 8 + 4];
            float fv[8] = {v0.x, v0.y, v0.z, v0.w, v1.x, v1.y, v1.z, v1.w};
#pragma unroll
            for (int i = 0; i < 6; i++)
#pragma unroll
                for (int j = 0; j < 8; j++)
                    acc[i][j] = fmaf(fa[i], fv[j], acc[i][j]);
        }
        __syncthreads();
    }

    float* yp = g_yt + (size_t)bh * DD * NN;
#pragma unroll
    for (int i = 0; i < 6; i++) {
        int d = ty * 6 + i;
        float4 o0 = {acc[i][0], acc[i][1], acc[i][2], acc[i][3]};
        float4 o1 = {acc[i][4], acc[i][5], acc[i][6], acc[i][7]};
        *(float4*)&yp[(size_t)d * NN + n0 + tx * 8]     = o0;
        *(float4*)&yp[(size_t)d * NN + n0 + tx * 8 + 4] = o1;
    }
}

// ---------------------------------------------------------------------------
extern "C" void kernel_launch(void* const* d_in, const int* in_sizes, int n_in,
                              void* d_out, int out_size)
{
    const float* x      = (const float*)d_in[0];
    const float* w_qkv  = (const float*)d_in[1];
    const float* w_proj = (const float*)d_in[2];
    const float* b_proj = (const float*)d_in[3];
    const float* temp   = (const float*)d_in[4];
    float* out = (float*)d_out;

    split_x_kernel<<<(BB * NN * CC / 4) / 256, 256>>>(x);
    split_wqkv_kernel<<<(CC * C3 / 4) / 256, 256>>>(w_qkv);
    split_wproj_kernel<<<(CC * CC / 4) / 256, 256>>>(w_proj);

    // GEMM1: [32768 x 1536] x [1536 x 2304] -> scatter q/k/v
    mma_gemm_kernel<<<dim3(C3 / 128, (BB * NN) / 128), 128>>>(C3, 0, nullptr, nullptr);

    norm_kernel<<<dim3(BH * DD, 2), 256>>>();
    attn_part_kernel<<<dim3(BH, SPLITS), 256>>>();
    softmax_kernel<<<BH * DD, 128>>>(temp);
    av_kernel<<<dim3(BH, NN / 128), 256>>>();

    ysplit_kernel<<<dim3(NN / 32, CC / 32, BB), dim3(32, 8)>>>();

    // GEMM2: [32768 x 1536] x [1536 x 768] -> out + bias
    mma_gemm_kernel<<<dim3(CC / 128, (BB * NN) / 128), 128>>>(CC, 1, b_proj, out);
}

// round 8
// speedup vs baseline: 1.3735x; 1.0887x over previous
#include <cuda_runtime.h>
#include <cuda_fp16.h>
#include <math.h>

// Problem constants
#define BB 8
#define NN 4096
#define CC 768
#define HH 8
#define DD 96
#define C3 2304
#define BH (BB*HH)
#define SPLITS 8
#define K3 1536          // 2*CC: fp16 split-K depth (A=[hi|lo], B=[hi;hi])
#define MTOT (BB*NN)     // 32768
#define NT (K3/32)       // 48 k-chunks

// Scratch (device globals — allocation-free kernel_launch)
__device__ float g_q[BB*HH*DD*NN];     // [b][h][d][n]
__device__ float g_k[BB*HH*DD*NN];
__device__ float g_v[BB*HH*DD*NN];
__device__ float g_rq[BB*HH*DD];
__device__ float g_rk[BB*HH*DD];
__device__ float g_part[SPLITS*BH*DD*DD];
__device__ float g_attn[BH*DD*DD];
__device__ float g_yt[BB*HH*DD*NN];    // y transposed: [b][c][n]

// fp16 split operands, K-MAJOR: A'[k][m]
__device__ __half g_xs[(size_t)K3*MTOT];    // GEMM1 A': rows 0..767 hi, 768..1535 lo
__device__ __half g_ys[(size_t)K3*MTOT];    // GEMM2 A'
__device__ __half g_ws[(size_t)K3*C3];      // GEMM1 B': [k][n], rows [hi;hi]
__device__ __half g_wps[(size_t)K3*CC];     // GEMM2 B'

// ---------------------------------------------------------------------------
// MMA / ldmatrix / cp.async helpers
// ---------------------------------------------------------------------------
__device__ __forceinline__ void mma16816(float* c, const unsigned* a, const unsigned* b) {
    asm volatile(
        "mma.sync.aligned.m16n8k16.row.col.f32.f16.f16.f32 "
        "{%0,%1,%2,%3}, {%4,%5,%6,%7}, {%8,%9}, {%0,%1,%2,%3};"
        : "+f"(c[0]), "+f"(c[1]), "+f"(c[2]), "+f"(c[3])
        : "r"(a[0]), "r"(a[1]), "r"(a[2]), "r"(a[3]), "r"(b[0]), "r"(b[1]));
}
__device__ __forceinline__ void ldsm_x4(unsigned* r, const void* p) {
    unsigned addr = (unsigned)__cvta_generic_to_shared(p);
    asm volatile("ldmatrix.sync.aligned.m8n8.x4.shared.b16 {%0,%1,%2,%3}, [%4];"
        : "=r"(r[0]), "=r"(r[1]), "=r"(r[2]), "=r"(r[3]) : "r"(addr));
}
__device__ __forceinline__ void ldsm_x4_t(unsigned* r, const void* p) {
    unsigned addr = (unsigned)__cvta_generic_to_shared(p);
    asm volatile("ldmatrix.sync.aligned.m8n8.x4.trans.shared.b16 {%0,%1,%2,%3}, [%4];"
        : "=r"(r[0]), "=r"(r[1]), "=r"(r[2]), "=r"(r[3]) : "r"(addr));
}
__device__ __forceinline__ void cp16(const void* smem_dst, const void* gsrc) {
    unsigned d = (unsigned)__cvta_generic_to_shared(smem_dst);
    asm volatile("cp.async.cg.shared.global [%0], [%1], 16;" :: "r"(d), "l"(gsrc));
}
#define CP_COMMIT() asm volatile("cp.async.commit_group;" ::: "memory")
#define CP_WAIT1()  asm volatile("cp.async.wait_group 1;" ::: "memory")

__device__ __forceinline__ void split_hl(float v, __half& hi, __half& lo) {
    hi = __float2half(v);
    lo = __float2half(v - __half2float(hi));
}
__device__ __forceinline__ void split4(float4 v, __half* h, __half* l) {
    split_hl(v.x, h[0], l[0]); split_hl(v.y, h[1], l[1]);
    split_hl(v.z, h[2], l[2]); split_hl(v.w, h[3], l[3]);
}

// ---------------------------------------------------------------------------
// split_x: x [m][c] fp32 -> g_xs [c(hi)|c+768(lo)][m] fp16 (smem transpose)
// ---------------------------------------------------------------------------
__global__ __launch_bounds__(256) void split_x_kernel(const float* __restrict__ x)
{
    __shared__ float sm[32][66];          // [c][m: 64] pad
    const int m0 = blockIdx.x * 64;
    const int c0 = blockIdx.y * 32;
    const int tx = threadIdx.x;           // 32 (c on read, m2 on write)
    const int ty = threadIdx.y;           // 8
#pragma unroll
    for (int i = 0; i < 8; i++) {
        int m = ty + i * 8;
        sm[tx][m] = x[(size_t)(m0 + m) * CC + c0 + tx];
    }
    __syncthreads();
#pragma unroll
    for (int i = 0; i < 4; i++) {
        int c = ty + i * 8;
        float v0 = sm[c][2 * tx], v1 = sm[c][2 * tx + 1];
        __half h0, l0, h1, l1;
        split_hl(v0, h0, l0); split_hl(v1, h1, l1);
        *(__half2*)&g_xs[(size_t)(c0 + c) * MTOT + m0 + 2 * tx]      = __halves2half2(h0, h1);
        *(__half2*)&g_xs[(size_t)(c0 + c + CC) * MTOT + m0 + 2 * tx] = __halves2half2(l0, l1);
    }
}

__global__ __launch_bounds__(256) void split_wqkv_kernel(const float* __restrict__ w)
{
    int idx = blockIdx.x * 256 + threadIdx.x;
    int k = idx / (C3 / 4);
    int n4 = (idx - k * (C3 / 4)) * 4;
    float4 v = *(const float4*)&w[(size_t)k * C3 + n4];
    __half hi[4];
    hi[0] = __float2half(v.x); hi[1] = __float2half(v.y);
    hi[2] = __float2half(v.z); hi[3] = __float2half(v.w);
    *(uint2*)&g_ws[(size_t)k * C3 + n4]        = *(uint2*)hi;
    *(uint2*)&g_ws[(size_t)(k + CC) * C3 + n4] = *(uint2*)hi;
}

__global__ __launch_bounds__(256) void split_wproj_kernel(const float* __restrict__ w)
{
    int idx = blockIdx.x * 256 + threadIdx.x;
    int k = idx / (CC / 4);
    int n4 = (idx - k * (CC / 4)) * 4;
    float4 v = *(const float4*)&w[(size_t)k * CC + n4];
    __half hi[4];
    hi[0] = __float2half(v.x); hi[1] = __float2half(v.y);
    hi[2] = __float2half(v.z); hi[3] = __float2half(v.w);
    *(uint2*)&g_wps[(size_t)k * CC + n4]        = *(uint2*)hi;
    *(uint2*)&g_wps[(size_t)(k + CC) * CC + n4] = *(uint2*)hi;
}

// ysplit: g_yt [b][c][n] fp32 -> g_ys [c(hi)|c+768(lo)][b*4096+n] fp16 (streaming)
__global__ __launch_bounds__(256) void ysplit_kernel()
{
    size_t idx8 = ((size_t)blockIdx.x * 256 + threadIdx.x) * 8;
    int b = (int)(idx8 / ((size_t)CC * NN));
    size_t r = idx8 - (size_t)b * CC * NN;
    int c = (int)(r / NN);
    int n = (int)(r - (size_t)c * NN);
    float4 f0 = *(const float4*)&g_yt[idx8];
    float4 f1 = *(const float4*)&g_yt[idx8 + 4];
    __half h[8], l[8];
    split4(f0, h, l); split4(f1, h + 4, l + 4);
    size_t mo = (size_t)b * NN + n;
    *(uint4*)&g_ys[(size_t)c * MTOT + mo]        = *(uint4*)h;
    *(uint4*)&g_ys[(size_t)(c + CC) * MTOT + mo] = *(uint4*)l;
}

// ---------------------------------------------------------------------------
// fp16 MMA GEMM, 3-stage cp.async pipeline, swizzled [k][*] tiles.
// BM=128, BN=128, BK=32. 128 threads = 4 warps (2x2), warp tile 64x64.
// mode 0: scatter into g_q/g_k/g_v.  mode 1: out = C + bias.
// ---------------------------------------------------------------------------
__global__ __launch_bounds__(128, 2) void mma_gemm_kernel(
    int Ncols, int mode, const float* __restrict__ bias, float* __restrict__ out)
{
    __shared__ __align__(16) __half As[3][32][128];   // [k][m], XOR-swizzled 16B groups
    __shared__ __align__(16) __half Bs[3][32][128];   // [k][n], XOR-swizzled
    const __half* __restrict__ A  = mode ? g_ys  : g_xs;
    const __half* __restrict__ Bm = mode ? g_wps : g_ws;

    const int tid = threadIdx.x;
    const int wid = tid >> 5, lane = tid & 31;
    const int rowBase = blockIdx.y * 128;
    const int colBase = blockIdx.x * 128;
    const int warpM = (wid & 1) * 64;
    const int warpN = (wid >> 1) * 64;

    float acc[4][8][4] = {};

    const int cg = tid & 15;     // 16B group 0..15
    const int rb = tid >> 4;     // row base 0..7

    auto load_stage = [&](int s, int t) {
        const __half* ap = A  + (size_t)(t * 32) * MTOT + rowBase;
        const __half* bp = Bm + (size_t)(t * 32) * Ncols + colBase;
#pragma unroll
        for (int p = 0; p < 4; p++) {
            int r = p * 8 + rb;
            int gp = (cg ^ (r & 7)) * 8;
            cp16(&As[s][r][gp], ap + (size_t)r * MTOT + cg * 8);
            cp16(&Bs[s][r][gp], bp + (size_t)r * Ncols + cg * 8);
        }
        CP_COMMIT();
    };

    load_stage(0, 0);
    load_stage(1, 1);

    for (int t = 0; t < NT; t++) {
        CP_WAIT1();
        __syncthreads();
        if (t + 2 < NT) load_stage((t + 2) % 3, t + 2);
        else            CP_COMMIT();
        const int s = t % 3;

#pragma unroll
        for (int ks = 0; ks < 2; ks++) {
            const int r = ks * 16 + ((lane >> 3) & 1) * 8 + (lane & 7);
            unsigned af[4][4];
#pragma unroll
            for (int im = 0; im < 4; im++) {
                int g = ((warpM + im * 16) >> 3) + (lane >> 4);
                unsigned r4[4];
                ldsm_x4_t(r4, &As[s][r][(g ^ (r & 7)) * 8]);
                af[im][0] = r4[0]; af[im][1] = r4[2];   // reorder: {r0,r2,r1,r3}
                af[im][2] = r4[1]; af[im][3] = r4[3];
            }
            unsigned bf[8][2];
#pragma unroll
            for (int gq = 0; gq < 4; gq++) {
                int g = ((warpN + gq * 16) >> 3) + (lane >> 4);
                unsigned r4[4];
                ldsm_x4_t(r4, &Bs[s][r][(g ^ (r & 7)) * 8]);
                bf[2 * gq][0] = r4[0]; bf[2 * gq][1] = r4[1];
                bf[2 * gq + 1][0] = r4[2]; bf[2 * gq + 1][1] = r4[3];
            }
#pragma unroll
            for (int im = 0; im < 4; im++)
#pragma unroll
                for (int jn = 0; jn < 8; jn++)
                    mma16816(acc[im][jn], af[im], bf[jn]);
        }
    }

    // Epilogue
#pragma unroll
    for (int im = 0; im < 4; im++) {
#pragma unroll
        for (int jn = 0; jn < 8; jn++) {
#pragma unroll
            for (int q = 0; q < 4; q++) {
                int m = warpM + im * 16 + (lane >> 2) + (q >> 1) * 8;
                int n = warpN + jn * 8 + (lane & 3) * 2 + (q & 1);
                float val = acc[im][jn][q];
                int row = rowBase + m;
                int col = colBase + n;
                if (mode == 0) {
                    int b = row >> 12;
                    int nn2 = row & 4095;
                    int h = col / 288;
                    int rem = col - h * 288;
                    int d = rem / 3;
                    int s3 = rem - d * 3;
                    float* dst = (s3 == 0) ? g_q : (s3 == 1) ? g_k : g_v;
                    dst[((b * HH + h) * DD + d) * NN + nn2] = val;
                } else {
                    out[(size_t)row * CC + col] = val + bias[col];
                }
            }
        }
    }
}

// ---------------------------------------------------------------------------
// norm: per-(b,h,d) inverse L2 norm over N for q (y=0) and k (y=1)
// ---------------------------------------------------------------------------
__global__ __launch_bounds__(256) void norm_kernel()
{
    const int row = blockIdx.x;
    const float* src = (blockIdx.y == 0) ? g_q : g_k;
    float*       dst = (blockIdx.y == 0) ? g_rq : g_rk;
    const float* p = src + (size_t)row * NN;
    float s = 0.f;
    for (int i = threadIdx.x; i < NN; i += 256) {
        float v = p[i];
        s = fmaf(v, v, s);
    }
#pragma unroll
    for (int off = 16; off; off >>= 1) s += __shfl_down_sync(0xffffffffu, s, off);
    __shared__ float ws[8];
    if ((threadIdx.x & 31) == 0) ws[threadIdx.x >> 5] = s;
    __syncthreads();
    if (threadIdx.x < 8) {
        float t = ws[threadIdx.x];
#pragma unroll
        for (int off = 4; off; off >>= 1) t += __shfl_down_sync(0xffu, t, off);
        if (threadIdx.x == 0) dst[row] = rsqrtf(t);
    }
}

// ---------------------------------------------------------------------------
// attn_part (tensor MMA): part[sp][bh][d][e] = sum_n q[d,n]k[e,n]
// fp16 hi/lo split on the fly; 3 terms (qh*kh + ql*kh + qh*kl).
// 128 thr = 4 warps (2x2), warp tile 48x48.
// ---------------------------------------------------------------------------
__global__ __launch_bounds__(128) void attn_part_kernel()
{
    __shared__ __align__(16) __half Qs[2][96][40];   // [hi/lo][d][n']
    __shared__ __align__(16) __half Ks[2][96][40];   // [hi/lo][e][n']
    const int tid = threadIdx.x;
    const int wid = tid >> 5, lane = tid & 31;
    const int bh = blockIdx.x;
    const int n0 = blockIdx.y * (NN / SPLITS);
    const float* qp = g_q + (size_t)bh * DD * NN;
    const float* kp = g_k + (size_t)bh * DD * NN;
    const int warpM = (wid & 1) * 48, warpN = (wid >> 1) * 48;

    float acc[3][6][4] = {};

    for (int nc = 0; nc < NN / SPLITS; nc += 32) {
        if (nc) __syncthreads();
#pragma unroll
        for (int p = 0; p < 6; p++) {
            int idx = p * 128 + tid;          // 768 float4s (96 rows x 8)
            int r = idx >> 3, c4 = (idx & 7) * 4;
            float4 qv = *(const float4*)&qp[(size_t)r * NN + n0 + nc + c4];
            float4 kv = *(const float4*)&kp[(size_t)r * NN + n0 + nc + c4];
            __half qh[4], ql[4], kh[4], kl[4];
            split4(qv, qh, ql); split4(kv, kh, kl);
            *(uint2*)&Qs[0][r][c4] = *(uint2*)qh;
            *(uint2*)&Qs[1][r][c4] = *(uint2*)ql;
            *(uint2*)&Ks[0][r][c4] = *(uint2*)kh;
            *(uint2*)&Ks[1][r][c4] = *(uint2*)kl;
        }
        __syncthreads();
#pragma unroll
        for (int term = 0; term < 3; term++) {
            const __half (*Aq)[40] = (term == 1) ? Qs[1] : Qs[0];
            const __half (*Bk)[40] = (term == 2) ? Ks[1] : Ks[0];
#pragma unroll
            for (int ks = 0; ks < 2; ks++) {
                unsigned af[3][4];
#pragma unroll
                for (int im = 0; im < 3; im++)
                    ldsm_x4(af[im], &Aq[warpM + im * 16 + (lane & 15)]
                                       [ks * 16 + (lane >> 4) * 8]);
                unsigned bf[6][2];
#pragma unroll
                for (int jg = 0; jg < 3; jg++) {
                    unsigned r4[4];
                    ldsm_x4(r4, &Bk[warpN + jg * 16 + (lane & 15)]
                                   [ks * 16 + (lane >> 4) * 8]);
                    bf[2 * jg][0] = r4[0]; bf[2 * jg][1] = r4[2];     // non-trans pairing
                    bf[2 * jg + 1][0] = r4[1]; bf[2 * jg + 1][1] = r4[3];
                }
#pragma unroll
                for (int im = 0; im < 3; im++)
#pragma unroll
                    for (int jn = 0; jn < 6; jn++)
                        mma16816(acc[im][jn], af[im], bf[jn]);
            }
        }
    }

    float* dst = g_part + ((size_t)blockIdx.y * BH + bh) * DD * DD;
#pragma unroll
    for (int im = 0; im < 3; im++)
#pragma unroll
        for (int jn = 0; jn < 6; jn++)
#pragma unroll
            for (int q = 0; q < 4; q++) {
                int row = warpM + im * 16 + (lane >> 2) + (q >> 1) * 8;
                int col = warpN + jn * 8 + (lane & 3) * 2 + (q & 1);
                dst[row * DD + col] = acc[im][jn][q];
            }
}

// ---------------------------------------------------------------------------
// softmax: reduce split-K partials, apply norms * temp, softmax over e.
// ---------------------------------------------------------------------------
__global__ __launch_bounds__(128) void softmax_kernel(const float* __restrict__ temp)
{
    const int bhd = blockIdx.x;
    const int bh = bhd / DD;
    const int d  = bhd - bh * DD;
    const int h  = bh & (HH - 1);
    const int e  = threadIdx.x;

    float raw = 0.f;
    float val = -1e30f;
    if (e < DD) {
        float s = 0.f;
#pragma unroll
        for (int sp = 0; sp < SPLITS; sp++)
            s += g_part[(((size_t)sp * BH + bh) * DD + d) * DD + e];
        raw = s * g_rq[bh * DD + d] * g_rk[bh * DD + e] * temp[h];
        val = raw;
    }

    __shared__ float red[128];
    red[e] = val;
    __syncthreads();
#pragma unroll
    for (int off = 64; off >= 1; off >>= 1) {
        if (e < off) red[e] = fmaxf(red[e], red[e + off]);
        __syncthreads();
    }
    float m = red[0];
    __syncthreads();

    float ex = (e < DD) ? expf(raw - m) : 0.f;
    red[e] = ex;
    __syncthreads();
#pragma unroll
    for (int off = 64; off >= 1; off >>= 1) {
        if (e < off) red[e] += red[e + off];
        __syncthreads();
    }
    float sum = red[0];

    if (e < DD)
        g_attn[((size_t)bh * DD + d) * DD + e] = ex / sum;
}

// ---------------------------------------------------------------------------
// av (tensor MMA): y_t[d][n] = sum_e attn[d][e] * v[e][n]
// fp16 hi/lo on the fly; 3 terms (ah*vh + al*vh + ah*vl).
// 128 thr = 4 warps (2x2), warp tile 48x64; e-chunks of 16.
// ---------------------------------------------------------------------------
__global__ __launch_bounds__(128) void av_kernel()
{
    __shared__ __align__(16) __half Ah[2][96][104];   // [hi/lo][d][e]
    __shared__ __align__(16) __half Vs[2][16][136];   // [hi/lo][e'][n]
    const int tid = threadIdx.x;
    const int wid = tid >> 5, lane = tid & 31;
    const int bh = blockIdx.x;
    const int n0 = blockIdx.y * 128;
    const float* ap = g_attn + (size_t)bh * DD * DD;
    const float* vp = g_v + (size_t)bh * DD * NN;
    const int warpM = (wid & 1) * 48, warpN = (wid >> 1) * 64;

    float acc[3][8][4] = {};

    // load attn 96x96 once, split
#pragma unroll
    for (int p = 0; p < 18; p++) {
        int idx = p * 128 + tid;              // 2304 float4s
        int r = idx / 24, c4 = (idx % 24) * 4;
        float4 v = *(const float4*)&ap[r * DD + c4];
        __half h[4], l[4];
        split4(v, h, l);
        *(uint2*)&Ah[0][r][c4] = *(uint2*)h;
        *(uint2*)&Ah[1][r][c4] = *(uint2*)l;
    }

    for (int ec = 0; ec < DD; ec += 16) {
        __syncthreads();
#pragma unroll
        for (int p = 0; p < 4; p++) {
            int idx = p * 128 + tid;          // 512 float4s (16 rows x 32)
            int r = idx >> 5, c4 = (idx & 31) * 4;
            float4 vv = *(const float4*)&vp[(size_t)(ec + r) * NN + n0 + c4];
            __half h[4], l[4];
            split4(vv, h, l);
            *(uint2*)&Vs[0][r][c4] = *(uint2*)h;
            *(uint2*)&Vs[1][r][c4] = *(uint2*)l;
        }
        __syncthreads();
#pragma unroll
        for (int term = 0; term < 3; term++) {
            const __half (*Aa)[104] = (term == 1) ? Ah[1] : Ah[0];
            const __half (*Vv)[136] = (term == 2) ? Vs[1] : Vs[0];
            unsigned af[3][4];
#pragma unroll
            for (int im = 0; im < 3; im++)
                ldsm_x4(af[im], &Aa[warpM + im * 16 + (lane & 15)]
                                   [ec + (lane >> 4) * 8]);
            unsigned bf[8][2];
#pragma unroll
            for (int g = 0; g < 4; g++) {
                unsigned r4[4];
                ldsm_x4_t(r4, &Vv[((lane >> 3) & 1) * 8 + (lane & 7)]
                              [warpN + g * 16 + (lane >> 4) * 8]);
                bf[2 * g][0] = r4[0]; bf[2 * g][1] = r4[1];           // trans pairing
                bf[2 * g + 1][0] = r4[2]; bf[2 * g + 1][1] = r4[3];
            }
#pragma unroll
            for (int im = 0; im < 3; im++)
#pragma unroll
                for (int jn = 0; jn < 8; jn++)
                    mma16816(acc[im][jn], af[im], bf[jn]);
        }
    }

    float* yp = g_yt + (size_t)bh * DD * NN;
#pragma unroll
    for (int im = 0; im < 3; im++)
#pragma unroll
        for (int jn = 0; jn < 8; jn++)
#pragma unroll
            for (int q = 0; q < 4; q++) {
                int row = warpM + im * 16 + (lane >> 2) + (q >> 1) * 8;
                int col = warpN + jn * 8 + (lane & 3) * 2 + (q & 1);
                yp[(size_t)row * NN + n0 + col] = acc[im][jn][q];
            }
}

// ---------------------------------------------------------------------------
extern "C" void kernel_launch(void* const* d_in, const int* in_sizes, int n_in,
                              void* d_out, int out_size)
{
    const float* x      = (const float*)d_in[0];
    const float* w_qkv  = (const float*)d_in[1];
    const float* w_proj = (const float*)d_in[2];
    const float* b_proj = (const float*)d_in[3];
    const float* temp   = (const float*)d_in[4];
    float* out = (float*)d_out;

    split_x_kernel<<<dim3(MTOT / 64, CC / 32), dim3(32, 8)>>>(x);
    split_wqkv_kernel<<<(CC * C3 / 4) / 256, 256>>>(w_qkv);
    split_wproj_kernel<<<(CC * CC / 4) / 256, 256>>>(w_proj);

    // GEMM1: scatter q/k/v
    mma_gemm_kernel<<<dim3(C3 / 128, MTOT / 128), 128>>>(C3, 0, nullptr, nullptr);

    norm_kernel<<<dim3(BH * DD, 2), 256>>>();
    attn_part_kernel<<<dim3(BH, SPLITS), 128>>>();
    softmax_kernel<<<BH * DD, 128>>>(temp);
    av_kernel<<<dim3(BH, NN / 128), 128>>>();

    ysplit_kernel<<<(BB * CC * NN / 8) / 256, 256>>>();

    // GEMM2: out = y @ W_proj + bias
    mma_gemm_kernel<<<dim3(CC / 128, MTOT / 128), 128>>>(CC, 1, b_proj, out);
}